// round 2
// baseline (speedup 1.0000x reference)
#include <cuda_runtime.h>
#include <cuda_bf16.h>
#include <math.h>

#define NROWS 100000
#define NGROUPS 25000   // NROWS/4
#define KSEL 15000
#define GB 592          // kernel B grid

static __device__ float    g_invn_sup[1024];        // support vector inv norms
static __device__ float    g_q[8192];               // normalized query per episode
static __device__ float    g_sim[NROWS * 8];        // sim[row][ep]
static __device__ float    g_invn[NROWS];           // base row inv norms
static __device__ unsigned g_thrkey[8];             // radix-select thresholds (key space)
static __device__ float    g_partials[GB * 8192];   // kernel B partial sums
static __device__ float    g_partial2[8 * 8192];    // stage-2 partials
static __device__ float    g_ahat[8192];            // normalized approx per episode

// ---------- helpers ----------
__device__ __forceinline__ void fma2(unsigned long long &d, unsigned long long a,
                                     unsigned long long b) {
    asm("fma.rn.f32x2 %0, %1, %2, %3;" : "=l"(d) : "l"(a), "l"(b), "l"(d));
}
__device__ __forceinline__ float psum2(unsigned long long v) {
    float a, b;
    asm("mov.b64 {%0, %1}, %2;" : "=f"(a), "=f"(b) : "l"(v));
    return a + b;
}
__device__ __forceinline__ unsigned tokey(float f) {
    unsigned u = __float_as_uint(f);
    return (u & 0x80000000u) ? ~u : (u | 0x80000000u);
}

template<int NW>
__device__ __forceinline__ float breduce(float v, float* sh) {
    #pragma unroll
    for (int o = 16; o > 0; o >>= 1) v += __shfl_down_sync(0xFFFFFFFFu, v, o);
    __syncthreads();
    if ((threadIdx.x & 31) == 0) sh[threadIdx.x >> 5] = v;
    __syncthreads();
    float s = 0.f;
    #pragma unroll
    for (int j = 0; j < NW; j++) s += sh[j];
    return s;
}

// ---------- Q1: inv norm of each support vector (1024 blocks x 256) ----------
__global__ void kQ1(const float* __restrict__ feat) {
    __shared__ float sh[8];
    int b = blockIdx.x;               // e*128 + s
    int e = b >> 7, s = b & 127;
    const float4* f4 = (const float4*)(feat + (size_t)(e * 1024 + s) * 1024);
    float4 f = f4[threadIdx.x];
    float ss = breduce<8>(f.x * f.x + f.y * f.y + f.z * f.z + f.w * f.w, sh);
    if (threadIdx.x == 0) g_invn_sup[b] = 1.0f / fmaxf(sqrtf(ss), 1e-12f);
}

// ---------- Q2: q[e] = norm(sum_s f_hat[e,s])  (8 blocks x 1024) ----------
__global__ void kQ2(const float* __restrict__ feat) {
    __shared__ float sh[32];
    int e = blockIdx.x, t = threadIdx.x;
    const float* fb = feat + (size_t)e * 1048576;
    const float* w  = g_invn_sup + e * 128;
    float acc = 0.f;
    #pragma unroll 4
    for (int s = 0; s < 128; s++) acc += fb[s * 1024 + t] * w[s];
    float ss = breduce<32>(acc * acc, sh);
    g_q[e * 1024 + t] = acc / fmaxf(sqrtf(ss), 1e-12f);
}

// ---------- A: sim[row][e] = dot(q_e, base_row)/||base_row||, invnorm ----------
__global__ __launch_bounds__(256) void kA(const float* __restrict__ base) {
    __shared__ __align__(16) float shq[8192];
    for (int j = threadIdx.x; j < 2048; j += 256)
        ((float4*)shq)[j] = ((const float4*)g_q)[j];
    __syncthreads();

    const ulonglong2* b2 = (const ulonglong2*)base;
    const ulonglong2* q2 = (const ulonglong2*)shq;
    int lane = threadIdx.x & 31, warp = threadIdx.x >> 5;
    int gw = blockIdx.x * 8 + warp, nwp = gridDim.x * 8;

    for (int g = gw; g < NGROUPS; g += nwp) {
        int row0 = g * 4;
        unsigned long long acc[4][9];
        #pragma unroll
        for (int r = 0; r < 4; r++)
            #pragma unroll
            for (int j = 0; j < 9; j++) acc[r][j] = 0ull;

        #pragma unroll
        for (int k = 0; k < 8; k++) {
            ulonglong2 x[4];
            #pragma unroll
            for (int r = 0; r < 4; r++)
                x[r] = b2[(size_t)(row0 + r) * 256 + k * 32 + lane];
            #pragma unroll
            for (int r = 0; r < 4; r++) {
                fma2(acc[r][8], x[r].x, x[r].x);
                fma2(acc[r][8], x[r].y, x[r].y);
            }
            #pragma unroll
            for (int e = 0; e < 8; e++) {
                ulonglong2 qv = q2[e * 256 + k * 32 + lane];
                #pragma unroll
                for (int r = 0; r < 4; r++) {
                    fma2(acc[r][e], x[r].x, qv.x);
                    fma2(acc[r][e], x[r].y, qv.y);
                }
            }
        }

        #pragma unroll
        for (int r = 0; r < 4; r++) {
            float red[9];
            #pragma unroll
            for (int j = 0; j < 9; j++) red[j] = psum2(acc[r][j]);
            #pragma unroll
            for (int o = 16; o > 0; o >>= 1) {
                #pragma unroll
                for (int j = 0; j < 9; j++)
                    red[j] += __shfl_down_sync(0xFFFFFFFFu, red[j], o);
            }
            if (lane == 0) {
                int i = row0 + r;
                float rn = 1.0f / fmaxf(sqrtf(red[8]), 1e-12f);
                g_invn[i] = rn;
                #pragma unroll
                for (int e = 0; e < 8; e++) g_sim[i * 8 + e] = red[e] * rn;
            }
        }
    }
}

// ---------- SEL: exact radix select of 15000th-largest sim per episode ----------
__global__ void kSEL() {
    __shared__ unsigned hist[256];
    __shared__ unsigned shp;
    __shared__ int shw;
    int e = blockIdx.x, tid = threadIdx.x;
    unsigned prefix = 0;
    int want = KSEL;

    for (int shift = 24; shift >= 0; shift -= 8) {
        for (int d = tid; d < 256; d += 1024) hist[d] = 0;
        __syncthreads();
        for (int i = tid; i < NROWS; i += 1024) {
            unsigned k = tokey(g_sim[i * 8 + e]);
            bool ok = (shift == 24) || (((k ^ prefix) >> (shift + 8)) == 0);
            if (ok) atomicAdd(&hist[(k >> shift) & 255], 1u);
        }
        __syncthreads();
        if (tid == 0) {
            int rem = want;
            unsigned d = 255;
            for (;;) {
                int c = (int)hist[d];
                if (c >= rem) break;
                rem -= c;
                if (d == 0) break;
                d--;
            }
            shp = prefix | (d << shift);
            shw = rem;
        }
        __syncthreads();
        prefix = shp;
        want = shw;
        __syncthreads();
    }
    if (tid == 0) g_thrkey[e] = prefix;
}

// ---------- B: partial weighted accumulation of selected normalized rows ----------
__global__ __launch_bounds__(256) void kB(const float* __restrict__ base) {
    int tid = threadIdx.x;
    unsigned tk[8];
    #pragma unroll
    for (int e = 0; e < 8; e++) tk[e] = g_thrkey[e];
    float4 acc[8];
    #pragma unroll
    for (int e = 0; e < 8; e++) acc[e] = make_float4(0.f, 0.f, 0.f, 0.f);

    const float4* b4 = (const float4*)base;
    for (int i = blockIdx.x; i < NROWS; i += 2 * GB) {
        int i2 = i + GB;
        const float4* s4 = (const float4*)(g_sim + (size_t)i * 8);
        float4 sa = s4[0], sb = s4[1];
        float s1[8] = {sa.x, sa.y, sa.z, sa.w, sb.x, sb.y, sb.z, sb.w};
        unsigned m1 = 0;
        #pragma unroll
        for (int e = 0; e < 8; e++) if (tokey(s1[e]) >= tk[e]) m1 |= 1u << e;

        unsigned m2 = 0;
        float s2[8];
        if (i2 < NROWS) {
            const float4* t4 = (const float4*)(g_sim + (size_t)i2 * 8);
            float4 ta = t4[0], tb = t4[1];
            s2[0] = ta.x; s2[1] = ta.y; s2[2] = ta.z; s2[3] = ta.w;
            s2[4] = tb.x; s2[5] = tb.y; s2[6] = tb.z; s2[7] = tb.w;
            #pragma unroll
            for (int e = 0; e < 8; e++) if (tokey(s2[e]) >= tk[e]) m2 |= 1u << e;
        }

        float4 x1, x2;
        float rn1 = 0.f, rn2 = 0.f;
        if (m1) { rn1 = g_invn[i];  x1 = b4[(size_t)i  * 256 + tid]; }
        if (m2) { rn2 = g_invn[i2]; x2 = b4[(size_t)i2 * 256 + tid]; }

        if (m1) {
            #pragma unroll
            for (int e = 0; e < 8; e++)
                if (m1 & (1u << e)) {
                    float s = sqrtf(s1[e]) * rn1;
                    acc[e].x += s * x1.x; acc[e].y += s * x1.y;
                    acc[e].z += s * x1.z; acc[e].w += s * x1.w;
                }
        }
        if (m2) {
            #pragma unroll
            for (int e = 0; e < 8; e++)
                if (m2 & (1u << e)) {
                    float s = sqrtf(s2[e]) * rn2;
                    acc[e].x += s * x2.x; acc[e].y += s * x2.y;
                    acc[e].z += s * x2.z; acc[e].w += s * x2.w;
                }
        }
    }

    float4* p4 = (float4*)g_partials;
    #pragma unroll
    for (int e = 0; e < 8; e++)
        p4[(size_t)blockIdx.x * 2048 + e * 256 + tid] = acc[e];
}

// ---------- R1: reduce 592 partials in 8 chunks of 74 (256 blocks x 256) ----------
__global__ void kR1() {
    int t = blockIdx.x * 256 + threadIdx.x;   // 0..65535
    int chunk = t >> 13, o = t & 8191;
    const float* p = g_partials + (size_t)(chunk * 74) * 8192 + o;
    float s = 0.f;
    #pragma unroll 2
    for (int j = 0; j < 74; j++) s += p[(size_t)j * 8192];
    g_partial2[chunk * 8192 + o] = s;
}

// ---------- R2: final reduce + normalize approx (8 blocks x 1024) ----------
__global__ void kR2() {
    __shared__ float sh[32];
    int e = blockIdx.x, t = threadIdx.x;
    int o = e * 1024 + t;
    float v = 0.f;
    #pragma unroll
    for (int c = 0; c < 8; c++) v += g_partial2[c * 8192 + o];
    float ss = breduce<32>(v * v, sh);
    g_ahat[o] = v / fmaxf(sqrtf(ss), 1e-12f);
}

// ---------- C: out = norm(f - (f.ahat) * ahat)  (8192 blocks x 256) ----------
__global__ void kC(const float* __restrict__ feat, float* __restrict__ out) {
    __shared__ float sh[8];
    int v = blockIdx.x;
    int e = v >> 10;
    const float4* f4 = (const float4*)feat + (size_t)v * 256;
    const float4* a4 = (const float4*)g_ahat + e * 256;
    float4 f = f4[threadIdx.x];
    float4 a = a4[threadIdx.x];
    float d = breduce<8>(f.x * a.x + f.y * a.y + f.z * a.z + f.w * a.w, sh);
    float4 w;
    w.x = f.x - d * a.x; w.y = f.y - d * a.y;
    w.z = f.z - d * a.z; w.w = f.w - d * a.w;
    float ss = breduce<8>(w.x * w.x + w.y * w.y + w.z * w.z + w.w * w.w, sh);
    float rn = 1.0f / fmaxf(sqrtf(ss), 1e-12f);
    float4 o4 = make_float4(w.x * rn, w.y * rn, w.z * rn, w.w * rn);
    ((float4*)out)[(size_t)v * 256 + threadIdx.x] = o4;
}

extern "C" void kernel_launch(void* const* d_in, const int* in_sizes, int n_in,
                              void* d_out, int out_size) {
    const float* feat = (const float*)d_in[0];
    const float* base = (const float*)d_in[1];
    (void)in_sizes; (void)n_in; (void)out_size;

    kQ1<<<1024, 256>>>(feat);
    kQ2<<<8, 1024>>>(feat);
    kA<<<296, 256>>>(base);
    kSEL<<<8, 1024>>>();
    kB<<<GB, 256>>>(base);
    kR1<<<256, 256>>>();
    kR2<<<8, 1024>>>();
    kC<<<8192, 256>>>(feat, (float*)d_out);
}

// round 3
// speedup vs baseline: 1.2389x; 1.2389x over previous
#include <cuda_runtime.h>
#include <cuda_bf16.h>
#include <math.h>

#define NROWS 100000
#define NGROUPS 25000   // NROWS/4
#define KSEL 15000
#define GB 592          // kernel B grid
#define CH  169         // rows per kB block (592*169 >= 100000)

static __device__ float    g_q[8192];                 // normalized query per episode
static __device__ float    g_simT[8 * NROWS];         // sim[e][row] (transposed)
static __device__ float    g_invn[NROWS];             // base row inv norms
static __device__ unsigned g_hists[2 * 8 * 65536];    // [pass][ep][bin]
static __device__ unsigned g_selp[8];                 // pass-1 selected hi-16 prefix
static __device__ int      g_selw[8];                 // remaining want after pass 1
static __device__ unsigned g_thrkey[8];               // final 32-bit threshold key
static __device__ unsigned char g_mask[NROWS];        // per-row episode bitmask
static __device__ float    g_wgt[NROWS * 8];          // per-row per-ep weight (0 if unselected)
static __device__ float    g_partials[GB * 8192];     // kernel B partial sums
static __device__ float    g_partial2[8 * 8192];      // stage-2 partials
static __device__ float    g_ahat[8192];              // normalized approx per episode

// ---------- helpers ----------
__device__ __forceinline__ void fma2(unsigned long long &d, unsigned long long a,
                                     unsigned long long b) {
    asm("fma.rn.f32x2 %0, %1, %2, %3;" : "=l"(d) : "l"(a), "l"(b), "l"(d));
}
__device__ __forceinline__ unsigned long long packff(float a, float b) {
    unsigned long long r;
    asm("mov.b64 %0, {%1, %2};" : "=l"(r) : "f"(a), "f"(b));
    return r;
}
__device__ __forceinline__ void unpackff(unsigned long long v, float &a, float &b) {
    asm("mov.b64 {%0, %1}, %2;" : "=f"(a), "=f"(b) : "l"(v));
}
__device__ __forceinline__ float psum2(unsigned long long v) {
    float a, b; unpackff(v, a, b); return a + b;
}
__device__ __forceinline__ unsigned tokey(float f) {
    unsigned u = __float_as_uint(f);
    return (u & 0x80000000u) ? ~u : (u | 0x80000000u);
}

template<int NW>
__device__ __forceinline__ float breduce(float v, float* sh) {
    #pragma unroll
    for (int o = 16; o > 0; o >>= 1) v += __shfl_down_sync(0xFFFFFFFFu, v, o);
    __syncthreads();
    if ((threadIdx.x & 31) == 0) sh[threadIdx.x >> 5] = v;
    __syncthreads();
    float s = 0.f;
    #pragma unroll
    for (int j = 0; j < NW; j++) s += sh[j];
    return s;
}

// ---------- Z: zero histograms (1024 blocks x 256, uint4 stores) ----------
__global__ void kZ() {
    int i = blockIdx.x * 256 + threadIdx.x;      // 262144 uint4 = 4MB
    ((uint4*)g_hists)[i] = make_uint4(0u, 0u, 0u, 0u);
}

// ---------- Q: fused support norms + query build (8 blocks x 1024) ----------
__global__ void kQ(const float* __restrict__ feat) {
    __shared__ float invn[128];
    __shared__ float sh[32];
    int e = blockIdx.x, t = threadIdx.x, warp = t >> 5, lane = t & 31;
    const float* fb = feat + (size_t)e * 1048576;

    // each warp computes norms of rows warp, warp+32, warp+64, warp+96
    #pragma unroll
    for (int r = warp; r < 128; r += 32) {
        const float4* f4 = (const float4*)(fb + (size_t)r * 1024);
        float ss = 0.f;
        #pragma unroll
        for (int j = lane; j < 256; j += 32) {
            float4 f = f4[j];
            ss += f.x * f.x + f.y * f.y + f.z * f.z + f.w * f.w;
        }
        #pragma unroll
        for (int o = 16; o > 0; o >>= 1) ss += __shfl_down_sync(0xFFFFFFFFu, ss, o);
        if (lane == 0) invn[r] = 1.0f / fmaxf(sqrtf(ss), 1e-12f);
    }
    __syncthreads();

    float acc = 0.f;
    #pragma unroll 8
    for (int s = 0; s < 128; s++) acc += fb[(size_t)s * 1024 + t] * invn[s];
    float ss = breduce<32>(acc * acc, sh);
    g_q[e * 1024 + t] = acc / fmaxf(sqrtf(ss), 1e-12f);
}

// ---------- A: simT[e][i] = dot(q_e, base_i)/||base_i||, invnorm ----------
__global__ __launch_bounds__(256) void kA(const float* __restrict__ base) {
    __shared__ __align__(16) float shq[8192];
    for (int j = threadIdx.x; j < 2048; j += 256)
        ((float4*)shq)[j] = ((const float4*)g_q)[j];
    __syncthreads();

    const ulonglong2* b2 = (const ulonglong2*)base;
    const ulonglong2* q2 = (const ulonglong2*)shq;
    int lane = threadIdx.x & 31, warp = threadIdx.x >> 5;
    int gw = blockIdx.x * 8 + warp, nwp = gridDim.x * 8;

    for (int g = gw; g < NGROUPS; g += nwp) {
        int row0 = g * 4;
        unsigned long long acc[4][9];
        #pragma unroll
        for (int r = 0; r < 4; r++)
            #pragma unroll
            for (int j = 0; j < 9; j++) acc[r][j] = 0ull;

        #pragma unroll
        for (int k = 0; k < 8; k++) {
            ulonglong2 x[4];
            #pragma unroll
            for (int r = 0; r < 4; r++)
                x[r] = b2[(size_t)(row0 + r) * 256 + k * 32 + lane];
            #pragma unroll
            for (int r = 0; r < 4; r++) {
                fma2(acc[r][8], x[r].x, x[r].x);
                fma2(acc[r][8], x[r].y, x[r].y);
            }
            #pragma unroll
            for (int e = 0; e < 8; e++) {
                ulonglong2 qv = q2[e * 256 + k * 32 + lane];
                #pragma unroll
                for (int r = 0; r < 4; r++) {
                    fma2(acc[r][e], x[r].x, qv.x);
                    fma2(acc[r][e], x[r].y, qv.y);
                }
            }
        }

        #pragma unroll
        for (int r = 0; r < 4; r++) {
            float red[9];
            #pragma unroll
            for (int j = 0; j < 9; j++) red[j] = psum2(acc[r][j]);
            #pragma unroll
            for (int o = 16; o > 0; o >>= 1) {
                #pragma unroll
                for (int j = 0; j < 9; j++)
                    red[j] += __shfl_down_sync(0xFFFFFFFFu, red[j], o);
            }
            if (lane == 0) {
                int i = row0 + r;
                float rn = 1.0f / fmaxf(sqrtf(red[8]), 1e-12f);
                g_invn[i] = rn;
                #pragma unroll
                for (int e = 0; e < 8; e++) g_simT[e * NROWS + i] = red[e] * rn;
            }
        }
    }
}

// ---------- H1: 16-bit histogram of sim keys (8*64 blocks x 256) ----------
__global__ void kH1() {
    int e = blockIdx.x >> 6, b = blockIdx.x & 63;
    const float* s = g_simT + (size_t)e * NROWS;
    unsigned* h = g_hists + (size_t)e * 65536;
    for (int i = b * 256 + threadIdx.x; i < NROWS; i += 64 * 256)
        atomicAdd(&h[tokey(s[i]) >> 16], 1u);
}

// ---------- P1: pick hi-16 prefix (8 blocks x 1024) ----------
__global__ void kP1() {
    __shared__ unsigned c[1024];
    int e = blockIdx.x, t = threadIdx.x;
    const unsigned* h = g_hists + (size_t)e * 65536;
    unsigned s = 0;
    #pragma unroll 8
    for (int j = 0; j < 64; j++) s += h[t * 64 + j];
    c[t] = s;
    __syncthreads();
    for (int off = 1; off < 1024; off <<= 1) {
        unsigned v = (t + off < 1024) ? c[t + off] : 0u;
        __syncthreads();
        c[t] += v;
        __syncthreads();
    }
    unsigned above = (t < 1023) ? c[t + 1] : 0u;
    if (c[t] >= KSEL && above < KSEL) {
        int rem = KSEL - (int)above;
        for (int b = t * 64 + 63; b >= t * 64; b--) {
            int cb = (int)h[b];
            if (cb >= rem) { g_selp[e] = (unsigned)b; g_selw[e] = rem; break; }
            rem -= cb;
        }
    }
}

// ---------- H2: low-16 histogram within chosen bucket ----------
__global__ void kH2() {
    int e = blockIdx.x >> 6, b = blockIdx.x & 63;
    unsigned p = g_selp[e];
    const float* s = g_simT + (size_t)e * NROWS;
    unsigned* h = g_hists + 524288 + (size_t)e * 65536;
    for (int i = b * 256 + threadIdx.x; i < NROWS; i += 64 * 256) {
        unsigned k = tokey(s[i]);
        if ((k >> 16) == p) atomicAdd(&h[k & 0xFFFFu], 1u);
    }
}

// ---------- P2: pick low-16 digit -> final threshold ----------
__global__ void kP2() {
    __shared__ unsigned c[1024];
    int e = blockIdx.x, t = threadIdx.x;
    const unsigned* h = g_hists + 524288 + (size_t)e * 65536;
    int K = g_selw[e];
    unsigned s = 0;
    #pragma unroll 8
    for (int j = 0; j < 64; j++) s += h[t * 64 + j];
    c[t] = s;
    __syncthreads();
    for (int off = 1; off < 1024; off <<= 1) {
        unsigned v = (t + off < 1024) ? c[t + off] : 0u;
        __syncthreads();
        c[t] += v;
        __syncthreads();
    }
    unsigned above = (t < 1023) ? c[t + 1] : 0u;
    if ((int)c[t] >= K && (int)above < K) {
        int rem = K - (int)above;
        for (int b = t * 64 + 63; b >= t * 64; b--) {
            int cb = (int)h[b];
            if (cb >= rem) {
                g_thrkey[e] = (g_selp[e] << 16) | (unsigned)b;
                break;
            }
            rem -= cb;
        }
    }
}

// ---------- M: per-row weights + mask (392 blocks x 256) ----------
__global__ void kM() {
    unsigned tk[8];
    #pragma unroll
    for (int e = 0; e < 8; e++) tk[e] = g_thrkey[e];
    for (int i = blockIdx.x * 256 + threadIdx.x; i < NROWS; i += gridDim.x * 256) {
        float rn = g_invn[i];
        float w[8]; unsigned m = 0;
        #pragma unroll
        for (int e = 0; e < 8; e++) {
            float sv = g_simT[(size_t)e * NROWS + i];
            bool sel = tokey(sv) >= tk[e];
            w[e] = sel ? sqrtf(sv) * rn : 0.f;
            if (sel) m |= 1u << e;
        }
        g_mask[i] = (unsigned char)m;
        float4* w4 = (float4*)(g_wgt + (size_t)i * 8);
        w4[0] = make_float4(w[0], w[1], w[2], w[3]);
        w4[1] = make_float4(w[4], w[5], w[6], w[7]);
    }
}

// ---------- B: compacted, branch-free weighted accumulation ----------
__global__ __launch_bounds__(256) void kB(const float* __restrict__ base) {
    __shared__ int list[CH];
    __shared__ int wcnt[8];
    int tid = threadIdx.x, lane = tid & 31, warp = tid >> 5;
    int r0 = blockIdx.x * CH;
    int nr = NROWS - r0; if (nr > CH) nr = CH; if (nr < 0) nr = 0;

    // deterministic ballot-based compaction of selected rows
    bool m = (tid < nr) && (g_mask[r0 + tid] != 0);
    unsigned bal = __ballot_sync(0xFFFFFFFFu, m);
    if (lane == 0) wcnt[warp] = __popc(bal);
    __syncthreads();
    int pre = 0;
    #pragma unroll
    for (int j = 0; j < 8; j++) if (j < warp) pre += wcnt[j];
    if (m) list[pre + __popc(bal & ((1u << lane) - 1u))] = r0 + tid;
    __syncthreads();
    int cnt = 0;
    #pragma unroll
    for (int j = 0; j < 8; j++) cnt += wcnt[j];

    unsigned long long acc[8][2];
    #pragma unroll
    for (int e = 0; e < 8; e++) { acc[e][0] = 0ull; acc[e][1] = 0ull; }

    const float4* b4 = (const float4*)base;

    int j = 0;
    for (; j + 2 <= cnt; j += 2) {
        int rA = list[j], rB = list[j + 1];
        float4 xA = __ldg(&b4[(size_t)rA * 256 + tid]);
        float4 xB = __ldg(&b4[(size_t)rB * 256 + tid]);
        const float4* wA = (const float4*)(g_wgt + (size_t)rA * 8);
        const float4* wB = (const float4*)(g_wgt + (size_t)rB * 8);
        float4 wa0 = __ldg(&wA[0]), wa1 = __ldg(&wA[1]);
        float4 wb0 = __ldg(&wB[0]), wb1 = __ldg(&wB[1]);
        float wfA[8] = {wa0.x, wa0.y, wa0.z, wa0.w, wa1.x, wa1.y, wa1.z, wa1.w};
        float wfB[8] = {wb0.x, wb0.y, wb0.z, wb0.w, wb1.x, wb1.y, wb1.z, wb1.w};
        unsigned long long xyA = packff(xA.x, xA.y), zwA = packff(xA.z, xA.w);
        unsigned long long xyB = packff(xB.x, xB.y), zwB = packff(xB.z, xB.w);
        #pragma unroll
        for (int e = 0; e < 8; e++) {
            unsigned long long wpA = packff(wfA[e], wfA[e]);
            fma2(acc[e][0], wpA, xyA);
            fma2(acc[e][1], wpA, zwA);
        }
        #pragma unroll
        for (int e = 0; e < 8; e++) {
            unsigned long long wpB = packff(wfB[e], wfB[e]);
            fma2(acc[e][0], wpB, xyB);
            fma2(acc[e][1], wpB, zwB);
        }
    }
    if (j < cnt) {
        int rA = list[j];
        float4 xA = __ldg(&b4[(size_t)rA * 256 + tid]);
        const float4* wA = (const float4*)(g_wgt + (size_t)rA * 8);
        float4 wa0 = __ldg(&wA[0]), wa1 = __ldg(&wA[1]);
        float wfA[8] = {wa0.x, wa0.y, wa0.z, wa0.w, wa1.x, wa1.y, wa1.z, wa1.w};
        unsigned long long xyA = packff(xA.x, xA.y), zwA = packff(xA.z, xA.w);
        #pragma unroll
        for (int e = 0; e < 8; e++) {
            unsigned long long wpA = packff(wfA[e], wfA[e]);
            fma2(acc[e][0], wpA, xyA);
            fma2(acc[e][1], wpA, zwA);
        }
    }

    float4* p4 = (float4*)g_partials;
    #pragma unroll
    for (int e = 0; e < 8; e++) {
        float a, b, c, d;
        unpackff(acc[e][0], a, b);
        unpackff(acc[e][1], c, d);
        p4[(size_t)blockIdx.x * 2048 + e * 256 + tid] = make_float4(a, b, c, d);
    }
}

// ---------- R1: reduce 592 partials in 8 chunks of 74 (256 blocks x 256) ----------
__global__ void kR1() {
    int t = blockIdx.x * 256 + threadIdx.x;   // 0..65535
    int chunk = t >> 13, o = t & 8191;
    const float* p = g_partials + (size_t)(chunk * 74) * 8192 + o;
    float s = 0.f;
    #pragma unroll 2
    for (int j = 0; j < 74; j++) s += p[(size_t)j * 8192];
    g_partial2[chunk * 8192 + o] = s;
}

// ---------- R2: final reduce + normalize approx (8 blocks x 1024) ----------
__global__ void kR2() {
    __shared__ float sh[32];
    int e = blockIdx.x, t = threadIdx.x;
    int o = e * 1024 + t;
    float v = 0.f;
    #pragma unroll
    for (int c = 0; c < 8; c++) v += g_partial2[c * 8192 + o];
    float ss = breduce<32>(v * v, sh);
    g_ahat[o] = v / fmaxf(sqrtf(ss), 1e-12f);
}

// ---------- C: out = norm(f - (f.ahat) * ahat)  (8192 blocks x 256) ----------
__global__ void kC(const float* __restrict__ feat, float* __restrict__ out) {
    __shared__ float sh[8];
    int v = blockIdx.x;
    int e = v >> 10;
    const float4* f4 = (const float4*)feat + (size_t)v * 256;
    const float4* a4 = (const float4*)g_ahat + e * 256;
    float4 f = f4[threadIdx.x];
    float4 a = a4[threadIdx.x];
    float d = breduce<8>(f.x * a.x + f.y * a.y + f.z * a.z + f.w * a.w, sh);
    float4 w;
    w.x = f.x - d * a.x; w.y = f.y - d * a.y;
    w.z = f.z - d * a.z; w.w = f.w - d * a.w;
    float ss = breduce<8>(w.x * w.x + w.y * w.y + w.z * w.z + w.w * w.w, sh);
    float rn = 1.0f / fmaxf(sqrtf(ss), 1e-12f);
    float4 o4 = make_float4(w.x * rn, w.y * rn, w.z * rn, w.w * rn);
    ((float4*)out)[(size_t)v * 256 + threadIdx.x] = o4;
}

extern "C" void kernel_launch(void* const* d_in, const int* in_sizes, int n_in,
                              void* d_out, int out_size) {
    const float* feat = (const float*)d_in[0];
    const float* base = (const float*)d_in[1];
    (void)in_sizes; (void)n_in; (void)out_size;

    kZ<<<1024, 256>>>();
    kQ<<<8, 1024>>>(feat);
    kA<<<296, 256>>>(base);
    kH1<<<512, 256>>>();
    kP1<<<8, 1024>>>();
    kH2<<<512, 256>>>();
    kP2<<<8, 1024>>>();
    kM<<<392, 256>>>();
    kB<<<GB, 256>>>(base);
    kR1<<<256, 256>>>();
    kR2<<<8, 1024>>>();
    kC<<<8192, 256>>>(feat, (float*)d_out);
}

// round 4
// speedup vs baseline: 1.3999x; 1.1299x over previous
#include <cuda_runtime.h>
#include <cuda_bf16.h>
#include <math.h>

#define NROWS 100000
#define NGROUPS 25000   // NROWS/4
#define KSEL 15000
#define GB 592          // kernel B grid
#define CH  169         // rows per kB block (592*169 >= 100000)

static __device__ float    g_invn_sup[1024];          // support vector inv norms
static __device__ float    g_qpart[256 * 1024];       // kQ2 partials
static __device__ float    g_q[8192];                 // normalized query per episode
static __device__ float    g_simT[8 * NROWS];         // sim[e][row] (transposed)
static __device__ float    g_invn[NROWS];             // base row inv norms
static __device__ unsigned g_hists[2 * 8 * 65536];    // [pass][ep][bin]
static __device__ unsigned g_selp[8];                 // pass-1 selected hi-16 prefix
static __device__ int      g_selw[8];                 // remaining want after pass 1
static __device__ unsigned g_thrkey[8];               // final 32-bit threshold key
static __device__ unsigned char g_mask[NROWS];        // per-row episode bitmask
static __device__ float    g_wgt[NROWS * 8];          // per-row per-ep weight
static __device__ float    g_partials[GB * 8192];     // kernel B partial sums
static __device__ float    g_partial2[8 * 8192];      // stage-2 partials
static __device__ float    g_ahat[8192];              // normalized approx per episode

// ---------- helpers ----------
__device__ __forceinline__ void fma2(unsigned long long &d, unsigned long long a,
                                     unsigned long long b) {
    asm("fma.rn.f32x2 %0, %1, %2, %3;" : "=l"(d) : "l"(a), "l"(b), "l"(d));
}
__device__ __forceinline__ unsigned long long packff(float a, float b) {
    unsigned long long r;
    asm("mov.b64 %0, {%1, %2};" : "=l"(r) : "f"(a), "f"(b));
    return r;
}
__device__ __forceinline__ void unpackff(unsigned long long v, float &a, float &b) {
    asm("mov.b64 {%0, %1}, %2;" : "=f"(a), "=f"(b) : "l"(v));
}
__device__ __forceinline__ float psum2(unsigned long long v) {
    float a, b; unpackff(v, a, b); return a + b;
}
__device__ __forceinline__ unsigned tokey(float f) {
    unsigned u = __float_as_uint(f);
    return (u & 0x80000000u) ? ~u : (u | 0x80000000u);
}
// warp-aggregated histogram add: lanes with equal bin merge into one atomic
__device__ __forceinline__ void aggAdd(unsigned* h, unsigned bin, unsigned mask) {
    unsigned m = __match_any_sync(mask, bin);
    int leader = __ffs(m) - 1;
    if ((int)(threadIdx.x & 31) == leader) atomicAdd(&h[bin], (unsigned)__popc(m));
}

template<int NW>
__device__ __forceinline__ float breduce(float v, float* sh) {
    #pragma unroll
    for (int o = 16; o > 0; o >>= 1) v += __shfl_down_sync(0xFFFFFFFFu, v, o);
    __syncthreads();
    if ((threadIdx.x & 31) == 0) sh[threadIdx.x >> 5] = v;
    __syncthreads();
    float s = 0.f;
    #pragma unroll
    for (int j = 0; j < NW; j++) s += sh[j];
    return s;
}

// ---------- Z: zero histograms (1024 blocks x 256, uint4 stores) ----------
__global__ void kZ() {
    int i = blockIdx.x * 256 + threadIdx.x;      // 262144 uint4 = 4MB
    ((uint4*)g_hists)[i] = make_uint4(0u, 0u, 0u, 0u);
}

// ---------- Q1: inv norm of each support vector (1024 blocks x 256) ----------
__global__ void kQ1(const float* __restrict__ feat) {
    __shared__ float sh[8];
    int b = blockIdx.x;               // e*128 + s
    int e = b >> 7, s = b & 127;
    const float4* f4 = (const float4*)(feat + (size_t)(e * 1024 + s) * 1024);
    float4 f = f4[threadIdx.x];
    float ss = breduce<8>(f.x * f.x + f.y * f.y + f.z * f.z + f.w * f.w, sh);
    if (threadIdx.x == 0) g_invn_sup[b] = 1.0f / fmaxf(sqrtf(ss), 1e-12f);
}

// ---------- Q2: partial weighted sum over 4 support rows (256 blocks x 1024) ----------
__global__ void kQ2(const float* __restrict__ feat) {
    int b = blockIdx.x, t = threadIdx.x;
    int e = b >> 5, c = b & 31;                 // rows c*4 .. c*4+3
    const float* fb = feat + (size_t)e * 1048576 + (size_t)c * 4 * 1024;
    const float* w  = g_invn_sup + e * 128 + c * 4;
    float acc = fb[t] * w[0] + fb[1024 + t] * w[1]
              + fb[2048 + t] * w[2] + fb[3072 + t] * w[3];
    g_qpart[(size_t)b * 1024 + t] = acc;
}

// ---------- Q3: reduce partials + normalize (8 blocks x 1024) ----------
__global__ void kQ3() {
    __shared__ float sh[32];
    int e = blockIdx.x, t = threadIdx.x;
    float v = 0.f;
    #pragma unroll
    for (int c = 0; c < 32; c++) v += g_qpart[(size_t)(e * 32 + c) * 1024 + t];
    float ss = breduce<32>(v * v, sh);
    g_q[e * 1024 + t] = v / fmaxf(sqrtf(ss), 1e-12f);
}

// ---------- A: simT[e][i] = dot(q_e, base_i)/||base_i||, invnorm ----------
__global__ __launch_bounds__(256) void kA(const float* __restrict__ base) {
    __shared__ __align__(16) float shq[8192];
    for (int j = threadIdx.x; j < 2048; j += 256)
        ((float4*)shq)[j] = ((const float4*)g_q)[j];
    __syncthreads();

    const ulonglong2* b2 = (const ulonglong2*)base;
    const ulonglong2* q2 = (const ulonglong2*)shq;
    int lane = threadIdx.x & 31, warp = threadIdx.x >> 5;
    int gw = blockIdx.x * 8 + warp, nwp = gridDim.x * 8;

    for (int g = gw; g < NGROUPS; g += nwp) {
        int row0 = g * 4;
        unsigned long long acc[4][9];
        #pragma unroll
        for (int r = 0; r < 4; r++)
            #pragma unroll
            for (int j = 0; j < 9; j++) acc[r][j] = 0ull;

        #pragma unroll
        for (int k = 0; k < 8; k++) {
            ulonglong2 x[4];
            #pragma unroll
            for (int r = 0; r < 4; r++)
                x[r] = b2[(size_t)(row0 + r) * 256 + k * 32 + lane];
            #pragma unroll
            for (int r = 0; r < 4; r++) {
                fma2(acc[r][8], x[r].x, x[r].x);
                fma2(acc[r][8], x[r].y, x[r].y);
            }
            #pragma unroll
            for (int e = 0; e < 8; e++) {
                ulonglong2 qv = q2[e * 256 + k * 32 + lane];
                #pragma unroll
                for (int r = 0; r < 4; r++) {
                    fma2(acc[r][e], x[r].x, qv.x);
                    fma2(acc[r][e], x[r].y, qv.y);
                }
            }
        }

        #pragma unroll
        for (int r = 0; r < 4; r++) {
            float red[9];
            #pragma unroll
            for (int j = 0; j < 9; j++) red[j] = psum2(acc[r][j]);
            #pragma unroll
            for (int o = 16; o > 0; o >>= 1) {
                #pragma unroll
                for (int j = 0; j < 9; j++)
                    red[j] += __shfl_down_sync(0xFFFFFFFFu, red[j], o);
            }
            if (lane == 0) {
                int i = row0 + r;
                float rn = 1.0f / fmaxf(sqrtf(red[8]), 1e-12f);
                g_invn[i] = rn;
                #pragma unroll
                for (int e = 0; e < 8; e++) g_simT[e * NROWS + i] = red[e] * rn;
            }
        }
    }
}

// ---------- H1: hi-16 histogram, float4 + warp-aggregated atomics ----------
__global__ void kH1() {
    int e = blockIdx.x >> 5, b = blockIdx.x & 31;
    const float4* s4 = (const float4*)(g_simT + (size_t)e * NROWS);
    unsigned* h = g_hists + (size_t)e * 65536;
    int t = b * 256 + threadIdx.x;               // 0..8191
    #pragma unroll
    for (int it = 0; it < 4; it++) {
        int i = t + it * 8192;
        bool in = i < NROWS / 4;
        unsigned mask = __ballot_sync(0xFFFFFFFFu, in);
        if (in) {
            float4 v = s4[i];
            aggAdd(h, tokey(v.x) >> 16, mask);
            aggAdd(h, tokey(v.y) >> 16, mask);
            aggAdd(h, tokey(v.z) >> 16, mask);
            aggAdd(h, tokey(v.w) >> 16, mask);
        }
    }
}

// ---------- P1: pick hi-16 prefix (8 blocks x 1024) ----------
__global__ void kP1() {
    __shared__ unsigned c[1024];
    int e = blockIdx.x, t = threadIdx.x;
    const unsigned* h = g_hists + (size_t)e * 65536;
    const uint4* h4 = (const uint4*)(h + t * 64);
    unsigned s = 0;
    #pragma unroll
    for (int j = 0; j < 16; j++) {
        uint4 u = h4[j];
        s += u.x + u.y + u.z + u.w;
    }
    c[t] = s;
    __syncthreads();
    for (int off = 1; off < 1024; off <<= 1) {
        unsigned v = (t + off < 1024) ? c[t + off] : 0u;
        __syncthreads();
        c[t] += v;
        __syncthreads();
    }
    unsigned above = (t < 1023) ? c[t + 1] : 0u;
    if (c[t] >= KSEL && above < KSEL) {
        int rem = KSEL - (int)above;
        for (int b = t * 64 + 63; b >= t * 64; b--) {
            int cb = (int)h[b];
            if (cb >= rem) { g_selp[e] = (unsigned)b; g_selw[e] = rem; break; }
            rem -= cb;
        }
    }
}

// ---------- H2: low-16 histogram within chosen bucket ----------
__global__ void kH2() {
    int e = blockIdx.x >> 5, b = blockIdx.x & 31;
    unsigned p = g_selp[e];
    const float4* s4 = (const float4*)(g_simT + (size_t)e * NROWS);
    unsigned* h = g_hists + 524288 + (size_t)e * 65536;
    int t = b * 256 + threadIdx.x;
    #pragma unroll
    for (int it = 0; it < 4; it++) {
        int i = t + it * 8192;
        bool in = i < NROWS / 4;
        float4 v;
        if (in) v = s4[i];
        unsigned k[4];
        if (in) { k[0] = tokey(v.x); k[1] = tokey(v.y); k[2] = tokey(v.z); k[3] = tokey(v.w); }
        #pragma unroll
        for (int j = 0; j < 4; j++) {
            bool ok = in && ((k[j] >> 16) == p);
            unsigned mk = __ballot_sync(0xFFFFFFFFu, ok);
            if (ok) aggAdd(h, k[j] & 0xFFFFu, mk);
        }
    }
}

// ---------- P2: pick low-16 digit -> final threshold ----------
__global__ void kP2() {
    __shared__ unsigned c[1024];
    int e = blockIdx.x, t = threadIdx.x;
    const unsigned* h = g_hists + 524288 + (size_t)e * 65536;
    int K = g_selw[e];
    const uint4* h4 = (const uint4*)(h + t * 64);
    unsigned s = 0;
    #pragma unroll
    for (int j = 0; j < 16; j++) {
        uint4 u = h4[j];
        s += u.x + u.y + u.z + u.w;
    }
    c[t] = s;
    __syncthreads();
    for (int off = 1; off < 1024; off <<= 1) {
        unsigned v = (t + off < 1024) ? c[t + off] : 0u;
        __syncthreads();
        c[t] += v;
        __syncthreads();
    }
    unsigned above = (t < 1023) ? c[t + 1] : 0u;
    if ((int)c[t] >= K && (int)above < K) {
        int rem = K - (int)above;
        for (int b = t * 64 + 63; b >= t * 64; b--) {
            int cb = (int)h[b];
            if (cb >= rem) {
                g_thrkey[e] = (g_selp[e] << 16) | (unsigned)b;
                break;
            }
            rem -= cb;
        }
    }
}

// ---------- M: per-row weights + mask (392 blocks x 256) ----------
__global__ void kM() {
    unsigned tk[8];
    #pragma unroll
    for (int e = 0; e < 8; e++) tk[e] = g_thrkey[e];
    for (int i = blockIdx.x * 256 + threadIdx.x; i < NROWS; i += gridDim.x * 256) {
        float rn = g_invn[i];
        float w[8]; unsigned m = 0;
        #pragma unroll
        for (int e = 0; e < 8; e++) {
            float sv = g_simT[(size_t)e * NROWS + i];
            bool sel = tokey(sv) >= tk[e];
            w[e] = sel ? sqrtf(sv) * rn : 0.f;
            if (sel) m |= 1u << e;
        }
        g_mask[i] = (unsigned char)m;
        float4* w4 = (float4*)(g_wgt + (size_t)i * 8);
        w4[0] = make_float4(w[0], w[1], w[2], w[3]);
        w4[1] = make_float4(w[4], w[5], w[6], w[7]);
    }
}

// ---------- B: compacted, branch-free weighted accumulation ----------
__global__ __launch_bounds__(256) void kB(const float* __restrict__ base) {
    __shared__ int list[CH];
    __shared__ int wcnt[8];
    int tid = threadIdx.x, lane = tid & 31, warp = tid >> 5;
    int r0 = blockIdx.x * CH;
    int nr = NROWS - r0; if (nr > CH) nr = CH; if (nr < 0) nr = 0;

    bool m = (tid < nr) && (g_mask[r0 + tid] != 0);
    unsigned bal = __ballot_sync(0xFFFFFFFFu, m);
    if (lane == 0) wcnt[warp] = __popc(bal);
    __syncthreads();
    int pre = 0;
    #pragma unroll
    for (int j = 0; j < 8; j++) if (j < warp) pre += wcnt[j];
    if (m) list[pre + __popc(bal & ((1u << lane) - 1u))] = r0 + tid;
    __syncthreads();
    int cnt = 0;
    #pragma unroll
    for (int j = 0; j < 8; j++) cnt += wcnt[j];

    unsigned long long acc[8][2];
    #pragma unroll
    for (int e = 0; e < 8; e++) { acc[e][0] = 0ull; acc[e][1] = 0ull; }

    const float4* b4 = (const float4*)base;

    int j = 0;
    for (; j + 2 <= cnt; j += 2) {
        int rA = list[j], rB = list[j + 1];
        float4 xA = __ldg(&b4[(size_t)rA * 256 + tid]);
        float4 xB = __ldg(&b4[(size_t)rB * 256 + tid]);
        const float4* wA = (const float4*)(g_wgt + (size_t)rA * 8);
        const float4* wB = (const float4*)(g_wgt + (size_t)rB * 8);
        float4 wa0 = __ldg(&wA[0]), wa1 = __ldg(&wA[1]);
        float4 wb0 = __ldg(&wB[0]), wb1 = __ldg(&wB[1]);
        float wfA[8] = {wa0.x, wa0.y, wa0.z, wa0.w, wa1.x, wa1.y, wa1.z, wa1.w};
        float wfB[8] = {wb0.x, wb0.y, wb0.z, wb0.w, wb1.x, wb1.y, wb1.z, wb1.w};
        unsigned long long xyA = packff(xA.x, xA.y), zwA = packff(xA.z, xA.w);
        unsigned long long xyB = packff(xB.x, xB.y), zwB = packff(xB.z, xB.w);
        #pragma unroll
        for (int e = 0; e < 8; e++) {
            unsigned long long wpA = packff(wfA[e], wfA[e]);
            fma2(acc[e][0], wpA, xyA);
            fma2(acc[e][1], wpA, zwA);
        }
        #pragma unroll
        for (int e = 0; e < 8; e++) {
            unsigned long long wpB = packff(wfB[e], wfB[e]);
            fma2(acc[e][0], wpB, xyB);
            fma2(acc[e][1], wpB, zwB);
        }
    }
    if (j < cnt) {
        int rA = list[j];
        float4 xA = __ldg(&b4[(size_t)rA * 256 + tid]);
        const float4* wA = (const float4*)(g_wgt + (size_t)rA * 8);
        float4 wa0 = __ldg(&wA[0]), wa1 = __ldg(&wA[1]);
        float wfA[8] = {wa0.x, wa0.y, wa0.z, wa0.w, wa1.x, wa1.y, wa1.z, wa1.w};
        unsigned long long xyA = packff(xA.x, xA.y), zwA = packff(xA.z, xA.w);
        #pragma unroll
        for (int e = 0; e < 8; e++) {
            unsigned long long wpA = packff(wfA[e], wfA[e]);
            fma2(acc[e][0], wpA, xyA);
            fma2(acc[e][1], wpA, zwA);
        }
    }

    float4* p4 = (float4*)g_partials;
    #pragma unroll
    for (int e = 0; e < 8; e++) {
        float a, b, c, d;
        unpackff(acc[e][0], a, b);
        unpackff(acc[e][1], c, d);
        p4[(size_t)blockIdx.x * 2048 + e * 256 + tid] = make_float4(a, b, c, d);
    }
}

// ---------- R1: reduce 592 partials in 8 chunks of 74 (256 blocks x 256) ----------
__global__ void kR1() {
    int t = blockIdx.x * 256 + threadIdx.x;   // 0..65535
    int chunk = t >> 13, o = t & 8191;
    const float* p = g_partials + (size_t)(chunk * 74) * 8192 + o;
    float s = 0.f;
    #pragma unroll 2
    for (int j = 0; j < 74; j++) s += p[(size_t)j * 8192];
    g_partial2[chunk * 8192 + o] = s;
}

// ---------- R2: final reduce + normalize approx (8 blocks x 1024) ----------
__global__ void kR2() {
    __shared__ float sh[32];
    int e = blockIdx.x, t = threadIdx.x;
    int o = e * 1024 + t;
    float v = 0.f;
    #pragma unroll
    for (int c = 0; c < 8; c++) v += g_partial2[c * 8192 + o];
    float ss = breduce<32>(v * v, sh);
    g_ahat[o] = v / fmaxf(sqrtf(ss), 1e-12f);
}

// ---------- C: out = norm(f - (f.ahat) * ahat)  (8192 blocks x 256) ----------
__global__ void kC(const float* __restrict__ feat, float* __restrict__ out) {
    __shared__ float sh[8];
    int v = blockIdx.x;
    int e = v >> 10;
    const float4* f4 = (const float4*)feat + (size_t)v * 256;
    const float4* a4 = (const float4*)g_ahat + e * 256;
    float4 f = f4[threadIdx.x];
    float4 a = a4[threadIdx.x];
    float d = breduce<8>(f.x * a.x + f.y * a.y + f.z * a.z + f.w * a.w, sh);
    float4 w;
    w.x = f.x - d * a.x; w.y = f.y - d * a.y;
    w.z = f.z - d * a.z; w.w = f.w - d * a.w;
    float ss = breduce<8>(w.x * w.x + w.y * w.y + w.z * w.z + w.w * w.w, sh);
    float rn = 1.0f / fmaxf(sqrtf(ss), 1e-12f);
    float4 o4 = make_float4(w.x * rn, w.y * rn, w.z * rn, w.w * rn);
    ((float4*)out)[(size_t)v * 256 + threadIdx.x] = o4;
}

extern "C" void kernel_launch(void* const* d_in, const int* in_sizes, int n_in,
                              void* d_out, int out_size) {
    const float* feat = (const float*)d_in[0];
    const float* base = (const float*)d_in[1];
    (void)in_sizes; (void)n_in; (void)out_size;

    kZ<<<1024, 256>>>();
    kQ1<<<1024, 256>>>(feat);
    kQ2<<<256, 1024>>>(feat);
    kQ3<<<8, 1024>>>();
    kA<<<296, 256>>>(base);
    kH1<<<256, 256>>>();
    kP1<<<8, 1024>>>();
    kH2<<<256, 256>>>();
    kP2<<<8, 1024>>>();
    kM<<<392, 256>>>();
    kB<<<GB, 256>>>(base);
    kR1<<<256, 256>>>();
    kR2<<<8, 1024>>>();
    kC<<<8192, 256>>>(feat, (float*)d_out);
}

// round 8
// speedup vs baseline: 2.5673x; 1.8339x over previous
#include <cuda_runtime.h>
#include <cuda_bf16.h>
#include <math.h>

#define NROWS 100000
#define KSEL 15000
#define NSTG 6250          // 16-row stages covering 100000 rows
#define GRIDP 148          // persistent grid for pipelined kernels

typedef unsigned long long ull;

static __device__ float    g_invn_sup[1024];
static __device__ float    g_qpart[256 * 1024];
static __device__ __align__(16) float g_q[8192];
static __device__ float    g_simT[8 * NROWS];
static __device__ float    g_invn[NROWS];
static __device__ unsigned g_hists[2 * 8 * 65536];
static __device__ unsigned g_selp[8];
static __device__ int      g_selw[8];
static __device__ unsigned g_thrkey[8];
static __device__ __align__(16) float g_wgt[NROWS * 8];   // per-row per-ep weight
static __device__ float    g_partials[GRIDP * 8192];
static __device__ float    g_ahat[8192];

// ---------- helpers ----------
__device__ __forceinline__ void fma2(ull &d, ull a, ull b) {
    asm("fma.rn.f32x2 %0, %1, %2, %3;" : "=l"(d) : "l"(a), "l"(b), "l"(d));
}
__device__ __forceinline__ ull packff(float a, float b) {
    ull r; asm("mov.b64 %0, {%1, %2};" : "=l"(r) : "f"(a), "f"(b)); return r;
}
__device__ __forceinline__ void unpackff(ull v, float &a, float &b) {
    asm("mov.b64 {%0, %1}, %2;" : "=f"(a), "=f"(b) : "l"(v));
}
__device__ __forceinline__ float psum2(ull v) { float a, b; unpackff(v, a, b); return a + b; }
__device__ __forceinline__ unsigned tokey(float f) {
    unsigned u = __float_as_uint(f);
    return (u & 0x80000000u) ? ~u : (u | 0x80000000u);
}
__device__ __forceinline__ void aggAdd(unsigned* h, unsigned bin, unsigned mask) {
    unsigned m = __match_any_sync(mask, bin);
    int leader = __ffs(m) - 1;
    if ((int)(threadIdx.x & 31) == leader) atomicAdd(&h[bin], (unsigned)__popc(m));
}
__device__ __forceinline__ unsigned s2u(const void* p) {
    unsigned a;
    asm("{ .reg .u64 t; cvta.to.shared.u64 t, %1; cvt.u32.u64 %0, t; }" : "=r"(a) : "l"(p));
    return a;
}
__device__ __forceinline__ void cpasync16(unsigned dst, const void* src) {
    asm volatile("cp.async.cg.shared.global [%0], [%1], 16;" :: "r"(dst), "l"(src) : "memory");
}
__device__ __forceinline__ void cpcommit() {
    asm volatile("cp.async.commit_group;" ::: "memory");
}
__device__ __forceinline__ void cpwait1() {
    asm volatile("cp.async.wait_group 1;" ::: "memory");
}

template<int NW>
__device__ __forceinline__ float breduce(float v, float* sh) {
    #pragma unroll
    for (int o = 16; o > 0; o >>= 1) v += __shfl_down_sync(0xFFFFFFFFu, v, o);
    __syncthreads();
    if ((threadIdx.x & 31) == 0) sh[threadIdx.x >> 5] = v;
    __syncthreads();
    float s = 0.f;
    #pragma unroll
    for (int j = 0; j < NW; j++) s += sh[j];
    return s;
}

extern __shared__ char dynsm[];

// ---------- Z: zero histograms ----------
__global__ void kZ() {
    int i = blockIdx.x * 256 + threadIdx.x;
    ((uint4*)g_hists)[i] = make_uint4(0u, 0u, 0u, 0u);
}

// ---------- Q1/Q2/Q3: build normalized query ----------
__global__ void kQ1(const float* __restrict__ feat) {
    __shared__ float sh[8];
    int b = blockIdx.x, e = b >> 7, s = b & 127;
    const float4* f4 = (const float4*)(feat + (size_t)(e * 1024 + s) * 1024);
    float4 f = f4[threadIdx.x];
    float ss = breduce<8>(f.x * f.x + f.y * f.y + f.z * f.z + f.w * f.w, sh);
    if (threadIdx.x == 0) g_invn_sup[b] = 1.0f / fmaxf(sqrtf(ss), 1e-12f);
}
__global__ void kQ2(const float* __restrict__ feat) {
    int b = blockIdx.x, t = threadIdx.x;
    int e = b >> 5, c = b & 31;
    const float* fb = feat + (size_t)e * 1048576 + (size_t)c * 4 * 1024;
    const float* w  = g_invn_sup + e * 128 + c * 4;
    float acc = fb[t] * w[0] + fb[1024 + t] * w[1]
              + fb[2048 + t] * w[2] + fb[3072 + t] * w[3];
    g_qpart[(size_t)b * 1024 + t] = acc;
}
__global__ void kQ3() {
    __shared__ float sh[32];
    int e = blockIdx.x, t = threadIdx.x;
    float v = 0.f;
    #pragma unroll
    for (int c = 0; c < 32; c++) v += g_qpart[(size_t)(e * 32 + c) * 1024 + t];
    float ss = breduce<32>(v * v, sh);
    g_q[e * 1024 + t] = v / fmaxf(sqrtf(ss), 1e-12f);
}

// ---------- A3: cp.async double-buffered sims + norms ----------
// smem: [0:32768) q, [32768:163840) 2 x 64KB row buffers
#define A3_SMEM 163840
__device__ __forceinline__ void a3_issue(unsigned dstb, const char* src, int tid) {
    #pragma unroll
    for (int j = 0; j < 16; j++)
        cpasync16(dstb + j * 4096 + tid * 16, src + j * 4096 + tid * 16);
}
__global__ __launch_bounds__(256) void kA3(const float* __restrict__ base) {
    float* qs = (float*)dynsm;
    unsigned bufb = s2u(dynsm + 32768);
    int tid = threadIdx.x, lane = tid & 31, w = tid >> 5;
    int bid = blockIdx.x;
    int nIter = (NSTG - bid + GRIDP - 1) / GRIDP;

    for (int j = tid; j < 2048; j += 256) ((float4*)qs)[j] = ((const float4*)g_q)[j];

    // prologue: always exactly 2 committed groups (second may be empty)
    a3_issue(bufb, (const char*)base + (size_t)bid * 65536, tid);
    cpcommit();
    if (nIter > 1)
        a3_issue(bufb + 65536, (const char*)base + ((size_t)bid + GRIDP) * 65536, tid);
    cpcommit();

    for (int i = 0; i < nIter; i++) {
        int st = i & 1;
        cpwait1();
        __syncthreads();
        const ulonglong2* xb = (const ulonglong2*)(dynsm + 32768 + st * 65536);
        const ulonglong2* q2 = (const ulonglong2*)qs;

        ull acc[2][9];
        #pragma unroll
        for (int r = 0; r < 2; r++)
            #pragma unroll
            for (int j = 0; j < 9; j++) acc[r][j] = 0ull;

        #pragma unroll
        for (int k = 0; k < 8; k++) {
            ulonglong2 x0 = xb[(w * 2) * 256 + k * 32 + lane];
            ulonglong2 x1 = xb[(w * 2 + 1) * 256 + k * 32 + lane];
            fma2(acc[0][8], x0.x, x0.x); fma2(acc[0][8], x0.y, x0.y);
            fma2(acc[1][8], x1.x, x1.x); fma2(acc[1][8], x1.y, x1.y);
            #pragma unroll
            for (int e = 0; e < 8; e++) {
                ulonglong2 qv = q2[e * 256 + k * 32 + lane];
                fma2(acc[0][e], x0.x, qv.x); fma2(acc[0][e], x0.y, qv.y);
                fma2(acc[1][e], x1.x, qv.x); fma2(acc[1][e], x1.y, qv.y);
            }
        }

        float red[2][9];
        #pragma unroll
        for (int r = 0; r < 2; r++)
            #pragma unroll
            for (int j = 0; j < 9; j++) red[r][j] = psum2(acc[r][j]);
        #pragma unroll
        for (int o = 16; o > 0; o >>= 1)
            #pragma unroll
            for (int r = 0; r < 2; r++)
                #pragma unroll
                for (int j = 0; j < 9; j++)
                    red[r][j] += __shfl_down_sync(0xFFFFFFFFu, red[r][j], o);

        if (lane == 0) {
            int row0 = (bid + i * GRIDP) * 16 + w * 2;
            #pragma unroll
            for (int r = 0; r < 2; r++) {
                float rn = 1.0f / fmaxf(sqrtf(red[r][8]), 1e-12f);
                g_invn[row0 + r] = rn;
                #pragma unroll
                for (int e = 0; e < 8; e++)
                    g_simT[(size_t)e * NROWS + row0 + r] = red[r][e] * rn;
            }
        }
        __syncthreads();   // all warps done reading buf[st] before refill
        if (i + 2 < nIter)
            a3_issue(bufb + st * 65536,
                     (const char*)base + ((size_t)bid + (size_t)(i + 2) * GRIDP) * 65536, tid);
        cpcommit();        // always commit (possibly empty group)
    }
}

// ---------- H1/P1/H2/P2: exact threshold select ----------
__global__ void kH1() {
    int e = blockIdx.x >> 5, b = blockIdx.x & 31;
    const float4* s4 = (const float4*)(g_simT + (size_t)e * NROWS);
    unsigned* h = g_hists + (size_t)e * 65536;
    int t = b * 256 + threadIdx.x;
    #pragma unroll
    for (int it = 0; it < 4; it++) {
        int i = t + it * 8192;
        bool in = i < NROWS / 4;
        unsigned mask = __ballot_sync(0xFFFFFFFFu, in);
        if (in) {
            float4 v = s4[i];
            aggAdd(h, tokey(v.x) >> 16, mask);
            aggAdd(h, tokey(v.y) >> 16, mask);
            aggAdd(h, tokey(v.z) >> 16, mask);
            aggAdd(h, tokey(v.w) >> 16, mask);
        }
    }
}
__global__ void kP1() {
    __shared__ unsigned c[1024];
    int e = blockIdx.x, t = threadIdx.x;
    const unsigned* h = g_hists + (size_t)e * 65536;
    const uint4* h4 = (const uint4*)(h + t * 64);
    unsigned s = 0;
    #pragma unroll
    for (int j = 0; j < 16; j++) { uint4 u = h4[j]; s += u.x + u.y + u.z + u.w; }
    c[t] = s;
    __syncthreads();
    for (int off = 1; off < 1024; off <<= 1) {
        unsigned v = (t + off < 1024) ? c[t + off] : 0u;
        __syncthreads();
        c[t] += v;
        __syncthreads();
    }
    unsigned above = (t < 1023) ? c[t + 1] : 0u;
    if (c[t] >= KSEL && above < KSEL) {
        int rem = KSEL - (int)above;
        for (int b = t * 64 + 63; b >= t * 64; b--) {
            int cb = (int)h[b];
            if (cb >= rem) { g_selp[e] = (unsigned)b; g_selw[e] = rem; break; }
            rem -= cb;
        }
    }
}
__global__ void kH2() {
    int e = blockIdx.x >> 5, b = blockIdx.x & 31;
    unsigned p = g_selp[e];
    const float4* s4 = (const float4*)(g_simT + (size_t)e * NROWS);
    unsigned* h = g_hists + 524288 + (size_t)e * 65536;
    int t = b * 256 + threadIdx.x;
    #pragma unroll
    for (int it = 0; it < 4; it++) {
        int i = t + it * 8192;
        bool in = i < NROWS / 4;
        float4 v;
        if (in) v = s4[i];
        unsigned k[4];
        if (in) { k[0] = tokey(v.x); k[1] = tokey(v.y); k[2] = tokey(v.z); k[3] = tokey(v.w); }
        #pragma unroll
        for (int j = 0; j < 4; j++) {
            bool ok = in && ((k[j] >> 16) == p);
            unsigned mk = __ballot_sync(0xFFFFFFFFu, ok);
            if (ok) aggAdd(h, k[j] & 0xFFFFu, mk);
        }
    }
}
__global__ void kP2() {
    __shared__ unsigned c[1024];
    int e = blockIdx.x, t = threadIdx.x;
    const unsigned* h = g_hists + 524288 + (size_t)e * 65536;
    int K = g_selw[e];
    const uint4* h4 = (const uint4*)(h + t * 64);
    unsigned s = 0;
    #pragma unroll
    for (int j = 0; j < 16; j++) { uint4 u = h4[j]; s += u.x + u.y + u.z + u.w; }
    c[t] = s;
    __syncthreads();
    for (int off = 1; off < 1024; off <<= 1) {
        unsigned v = (t + off < 1024) ? c[t + off] : 0u;
        __syncthreads();
        c[t] += v;
        __syncthreads();
    }
    unsigned above = (t < 1023) ? c[t + 1] : 0u;
    if ((int)c[t] >= K && (int)above < K) {
        int rem = K - (int)above;
        for (int b = t * 64 + 63; b >= t * 64; b--) {
            int cb = (int)h[b];
            if (cb >= rem) { g_thrkey[e] = (g_selp[e] << 16) | (unsigned)b; break; }
            rem -= cb;
        }
    }
}

// ---------- M: per-row weights ----------
__global__ void kM() {
    unsigned tk[8];
    #pragma unroll
    for (int e = 0; e < 8; e++) tk[e] = g_thrkey[e];
    for (int i = blockIdx.x * 256 + threadIdx.x; i < NROWS; i += gridDim.x * 256) {
        float rn = g_invn[i];
        float w[8];
        #pragma unroll
        for (int e = 0; e < 8; e++) {
            float sv = g_simT[(size_t)e * NROWS + i];
            bool sel = tokey(sv) >= tk[e];
            w[e] = sel ? sqrtf(sv) * rn : 0.f;
        }
        float4* w4 = (float4*)(g_wgt + (size_t)i * 8);
        w4[0] = make_float4(w[0], w[1], w[2], w[3]);
        w4[1] = make_float4(w[4], w[5], w[6], w[7]);
    }
}

// ---------- B3: cp.async double-buffered branch-free weighted accumulation ----------
// smem: [0:2048) 2 x 1KB weight buffers, [2048:133120) 2 x 64KB row buffers
#define B3_SMEM 133120
__device__ __forceinline__ void b3_issue(unsigned xb_b, unsigned wb_b, int st,
                                         size_t sIdx, const char* baseb, int tid) {
    const char* xs = baseb + sIdx * 65536;
    #pragma unroll
    for (int j = 0; j < 16; j++)
        cpasync16(xb_b + st * 65536 + j * 4096 + tid * 16, xs + j * 4096 + tid * 16);
    if (tid < 32)
        cpasync16(wb_b + st * 1024 + tid * 16,
                  (const char*)g_wgt + sIdx * 512 + tid * 16);
}
__global__ __launch_bounds__(256) void kB3(const float* __restrict__ base) {
    unsigned wb_b = s2u(dynsm);
    unsigned xb_b = s2u(dynsm + 2048);
    int tid = threadIdx.x;
    int bid = blockIdx.x;
    int nIter = (NSTG - bid + GRIDP - 1) / GRIDP;
    const char* baseb = (const char*)base;

    b3_issue(xb_b, wb_b, 0, (size_t)bid, baseb, tid);
    cpcommit();
    if (nIter > 1)
        b3_issue(xb_b, wb_b, 1, (size_t)bid + GRIDP, baseb, tid);
    cpcommit();

    ull acc[16];
    #pragma unroll
    for (int j = 0; j < 16; j++) acc[j] = 0ull;

    for (int i = 0; i < nIter; i++) {
        int st = i & 1;
        cpwait1();
        __syncthreads();
        const float4* xb = (const float4*)(dynsm + 2048 + st * 65536);
        const float4* wb = (const float4*)(dynsm + st * 1024);

        #pragma unroll 4
        for (int lr = 0; lr < 16; lr++) {
            float4 x = xb[lr * 256 + tid];
            float4 w0 = wb[lr * 2], w1 = wb[lr * 2 + 1];
            ull xy = packff(x.x, x.y), zw = packff(x.z, x.w);
            float wf[8] = {w0.x, w0.y, w0.z, w0.w, w1.x, w1.y, w1.z, w1.w};
            #pragma unroll
            for (int e = 0; e < 8; e++) {
                ull wp = packff(wf[e], wf[e]);
                fma2(acc[e * 2], wp, xy);
                fma2(acc[e * 2 + 1], wp, zw);
            }
        }
        __syncthreads();
        if (i + 2 < nIter)
            b3_issue(xb_b, wb_b, st, (size_t)bid + (size_t)(i + 2) * GRIDP, baseb, tid);
        cpcommit();
    }

    float4* p4 = (float4*)g_partials;
    #pragma unroll
    for (int e = 0; e < 8; e++) {
        float a, b, c, d;
        unpackff(acc[e * 2], a, b);
        unpackff(acc[e * 2 + 1], c, d);
        p4[(size_t)bid * 2048 + e * 256 + tid] = make_float4(a, b, c, d);
    }
}

// ---------- R: reduce 148 partials + normalize (8 blocks x 1024) ----------
__global__ void kR() {
    __shared__ float sh[32];
    int e = blockIdx.x, t = threadIdx.x;
    float v = 0.f;
    #pragma unroll 4
    for (int b = 0; b < GRIDP; b++) v += g_partials[(size_t)b * 8192 + e * 1024 + t];
    float ss = breduce<32>(v * v, sh);
    g_ahat[e * 1024 + t] = v / fmaxf(sqrtf(ss), 1e-12f);
}

// ---------- C: out = norm(f - (f.ahat) * ahat) ----------
__global__ void kC(const float* __restrict__ feat, float* __restrict__ out) {
    __shared__ float sh[8];
    int v = blockIdx.x;
    int e = v >> 10;
    const float4* f4 = (const float4*)feat + (size_t)v * 256;
    const float4* a4 = (const float4*)g_ahat + e * 256;
    float4 f = f4[threadIdx.x];
    float4 a = a4[threadIdx.x];
    float d = breduce<8>(f.x * a.x + f.y * a.y + f.z * a.z + f.w * a.w, sh);
    float4 w;
    w.x = f.x - d * a.x; w.y = f.y - d * a.y;
    w.z = f.z - d * a.z; w.w = f.w - d * a.w;
    float ss = breduce<8>(w.x * w.x + w.y * w.y + w.z * w.z + w.w * w.w, sh);
    float rn = 1.0f / fmaxf(sqrtf(ss), 1e-12f);
    ((float4*)out)[(size_t)v * 256 + threadIdx.x] =
        make_float4(w.x * rn, w.y * rn, w.z * rn, w.w * rn);
}

extern "C" void kernel_launch(void* const* d_in, const int* in_sizes, int n_in,
                              void* d_out, int out_size) {
    const float* feat = (const float*)d_in[0];
    const float* base = (const float*)d_in[1];
    (void)in_sizes; (void)n_in; (void)out_size;

    // host-side, idempotent, capture-legal; needed for >48KB dynamic smem
    cudaFuncSetAttribute(kA3, cudaFuncAttributeMaxDynamicSharedMemorySize, A3_SMEM);
    cudaFuncSetAttribute(kB3, cudaFuncAttributeMaxDynamicSharedMemorySize, B3_SMEM);

    kQ1<<<1024, 256>>>(feat);
    kQ2<<<256, 1024>>>(feat);
    kQ3<<<8, 1024>>>();
    kA3<<<GRIDP, 256, A3_SMEM>>>(base);   // 4th launch -> gets profiled
    kZ<<<1024, 256>>>();
    kH1<<<256, 256>>>();
    kP1<<<8, 1024>>>();
    kH2<<<256, 256>>>();
    kP2<<<8, 1024>>>();
    kM<<<392, 256>>>();
    kB3<<<GRIDP, 256, B3_SMEM>>>(base);
    kR<<<8, 1024>>>();
    kC<<<8192, 256>>>(feat, (float*)d_out);
}